// round 1
// baseline (speedup 1.0000x reference)
#include <cuda_runtime.h>
#include <math.h>

#define BATCH 1048576
#define NANCH 3
#define NGT   8
#define LAMBDA_COORD 5.0f

__device__ double g_acc;

__global__ void zero_acc_kernel() {
    g_acc = 0.0;
}

__global__ void __launch_bounds__(256) yolo_loss_kernel(
    const float4* __restrict__ pred4,   // (B, 3, 8) floats -> 6 float4 per batch
    const float4* __restrict__ gtb4,    // (B, 8, 4) floats -> 8 float4 per batch
    const int4*   __restrict__ gtc4)    // (B, 8) ints      -> 2 int4 per batch
{
    const int b = blockIdx.x * blockDim.x + threadIdx.x;
    float lsum = 0.0f;

    if (b < BATCH) {
        // ---- load gt boxes + classes for this batch row ----
        float4 g[NGT];
        #pragma unroll
        for (int j = 0; j < NGT; ++j) g[j] = gtb4[(size_t)b * NGT + j];
        const int4 ca = gtc4[(size_t)b * 2 + 0];
        const int4 cb = gtc4[(size_t)b * 2 + 1];
        const int cls[NGT] = {ca.x, ca.y, ca.z, ca.w, cb.x, cb.y, cb.z, cb.w};

        #pragma unroll
        for (int a = 0; a < NANCH; ++a) {
            const float4 p0 = pred4[(size_t)b * 6 + a * 2 + 0];
            const float4 p1 = pred4[(size_t)b * 6 + a * 2 + 1];

            const float px    = 1.0f / (1.0f + __expf(-p0.x));
            const float py    = 1.0f / (1.0f + __expf(-p0.y));
            const float pw    = p0.z;
            const float ph    = p0.w;
            const float pconf = 1.0f / (1.0f + __expf(-p1.x));
            const float l0 = p1.y, l1 = p1.z, l2 = p1.w;

            const float px1 = px - pw * 0.5f;
            const float px2 = px + pw * 0.5f;
            const float py1 = py - ph * 0.5f;
            const float py2 = py + ph * 0.5f;
            const float parea = (px2 - px1) * (py2 - py1);   // match reference exactly

            // ---- best IoU over 8 gt boxes (first-occurrence argmax) ----
            float best = -INFINITY;
            float bx = 0.f, by = 0.f, bw = 0.f, bh = 0.f;
            int   bcls = 0;
            #pragma unroll
            for (int j = 0; j < NGT; ++j) {
                const float gw  = g[j].z, gh = g[j].w;
                const float gx1 = g[j].x - gw * 0.5f;
                const float gx2 = g[j].x + gw * 0.5f;
                const float gy1 = g[j].y - gh * 0.5f;
                const float gy2 = g[j].y + gh * 0.5f;
                float iw = fminf(px2, gx2) - fmaxf(px1, gx1);
                float ih = fminf(py2, gy2) - fmaxf(py1, gy1);
                iw = fmaxf(iw, 0.0f);
                ih = fmaxf(ih, 0.0f);
                const float inter = iw * ih;
                const float garea = (gx2 - gx1) * (gy2 - gy1);
                const float iou = inter / (parea + garea - inter + 1e-6f);
                if (iou > best) {
                    best = iou;
                    bx = g[j].x; by = g[j].y; bw = g[j].z; bh = g[j].w;
                    bcls = cls[j];
                }
            }

            if (best > 0.5f) {
                // matched: coord + conf(-log p) + class NLL
                const float dx = px - bx, dy = py - by, dw = pw - bw, dh = ph - bh;
                const float coord = dx * dx + dy * dy + dw * dw + dh * dh;
                const float logp = fmaxf(__logf(pconf), -100.0f);
                const float mx  = fmaxf(l0, fmaxf(l1, l2));
                const float lse = mx + __logf(__expf(l0 - mx) + __expf(l1 - mx) + __expf(l2 - mx));
                const float lc  = (bcls == 0) ? l0 : ((bcls == 1) ? l1 : l2);
                const float nll = lse - lc;
                lsum += LAMBDA_COORD * coord - logp + nll;
            } else {
                // unmatched: conf(-log(1-p))
                const float log1mp = fmaxf(log1pf(-pconf), -100.0f);
                lsum += -log1mp;
            }
        }
    }

    // ---- block reduction -> double atomic ----
    #pragma unroll
    for (int o = 16; o > 0; o >>= 1)
        lsum += __shfl_down_sync(0xFFFFFFFFu, lsum, o);

    __shared__ float ssum[8];
    const int lane = threadIdx.x & 31;
    const int wid  = threadIdx.x >> 5;
    if (lane == 0) ssum[wid] = lsum;
    __syncthreads();
    if (threadIdx.x < 8) {
        float v = ssum[threadIdx.x];
        #pragma unroll
        for (int o = 4; o > 0; o >>= 1)
            v += __shfl_down_sync(0xFFu, v, o);
        if (threadIdx.x == 0)
            atomicAdd(&g_acc, (double)v);
    }
}

__global__ void finalize_kernel(float* __restrict__ out) {
    out[0] = (float)(g_acc / (double)BATCH);
}

extern "C" void kernel_launch(void* const* d_in, const int* in_sizes, int n_in,
                              void* d_out, int out_size) {
    const float4* pred4 = (const float4*)d_in[0];
    const float4* gtb4  = (const float4*)d_in[1];
    const int4*   gtc4  = (const int4*)d_in[2];
    float* out = (float*)d_out;

    zero_acc_kernel<<<1, 1>>>();
    yolo_loss_kernel<<<(BATCH + 255) / 256, 256>>>(pred4, gtb4, gtc4);
    finalize_kernel<<<1, 1>>>(out);
}

// round 2
// speedup vs baseline: 1.8239x; 1.8239x over previous
#include <cuda_runtime.h>
#include <math.h>

#define BATCH   1048576
#define NANCH   3
#define NGT     8
#define NTHREAD (BATCH * NANCH)
#define TPB     256
#define NBLK    (NTHREAD / TPB)       // 12288
#define LAMBDA_COORD 5.0f

__device__ float g_partial[NBLK];

__global__ void __launch_bounds__(TPB) yolo_loss_kernel(
    const float4* __restrict__ pred4,   // (B, 3, 8) floats -> 2 float4 per anchor
    const float4* __restrict__ gtb4,    // (B, 8, 4) floats -> 8 float4 per row
    const int*    __restrict__ gtc)     // (B, 8) ints
{
    const int idx = blockIdx.x * blockDim.x + threadIdx.x;   // (row, anchor)
    const int row = idx / 3;

    // ---- per-anchor prediction ----
    const float4 p0 = pred4[(size_t)idx * 2 + 0];
    const float4 p1 = pred4[(size_t)idx * 2 + 1];

    const float px = __fdividef(1.0f, 1.0f + __expf(-p0.x));
    const float py = __fdividef(1.0f, 1.0f + __expf(-p0.y));
    const float pw = p0.z;
    const float ph = p0.w;
    const float xc = p1.x;                 // raw conf logit
    const float l0 = p1.y, l1 = p1.z, l2 = p1.w;

    const float px1 = px - pw * 0.5f;
    const float px2 = px + pw * 0.5f;
    const float py1 = py - ph * 0.5f;
    const float py2 = py + ph * 0.5f;
    const float parea = (px2 - px1) * (py2 - py1);

    // ---- stream 8 gt boxes, division-free first-occurrence argmax ----
    const size_t gbase = (size_t)row * NGT;
    float best_inter, best_den;
    float bx, by, bw, bh;
    int   bestj = 0;

    {
        const float4 g0 = gtb4[gbase];
        const float gw = g0.z, gh = g0.w;
        const float gx1 = g0.x - gw * 0.5f, gx2 = g0.x + gw * 0.5f;
        const float gy1 = g0.y - gh * 0.5f, gy2 = g0.y + gh * 0.5f;
        const float iw = fmaxf(fminf(px2, gx2) - fmaxf(px1, gx1), 0.0f);
        const float ih = fmaxf(fminf(py2, gy2) - fmaxf(py1, gy1), 0.0f);
        best_inter = iw * ih;
        best_den   = parea + (gx2 - gx1) * (gy2 - gy1) - best_inter + 1e-6f;
        bx = g0.x; by = g0.y; bw = gw; bh = gh;
    }

    #pragma unroll
    for (int j = 1; j < NGT; ++j) {
        const float4 g = gtb4[gbase + j];
        const float gw = g.z, gh = g.w;
        const float gx1 = g.x - gw * 0.5f, gx2 = g.x + gw * 0.5f;
        const float gy1 = g.y - gh * 0.5f, gy2 = g.y + gh * 0.5f;
        const float iw = fmaxf(fminf(px2, gx2) - fmaxf(px1, gx1), 0.0f);
        const float ih = fmaxf(fminf(py2, gy2) - fmaxf(py1, gy1), 0.0f);
        const float inter = iw * ih;
        const float den   = parea + (gx2 - gx1) * (gy2 - gy1) - inter + 1e-6f;
        // iou_j > iou_best  <=>  (inter*best_den - best_inter*den) * (den*best_den) > 0
        const float diff = inter * best_den - best_inter * den;
        const float sgn  = den * best_den;
        if (diff * sgn > 0.0f) {
            best_inter = inter; best_den = den;
            bx = g.x; by = g.y; bw = gw; bh = gh;
            bestj = j;
        }
    }

    const bool matched = (best_den > 0.0f) && (2.0f * best_inter > best_den);

    // ---- conf loss: softplus of (+/-) raw logit, clamped at 100 ----
    const float t  = matched ? -xc : xc;
    const float sp = fmaxf(t, 0.0f) + __logf(1.0f + __expf(-fabsf(t)));
    float lsum = fminf(sp, 100.0f);

    if (matched) {
        const float dx = px - bx, dy = py - by, dw = pw - bw, dh = ph - bh;
        lsum += LAMBDA_COORD * (dx * dx + dy * dy + dw * dw + dh * dh);
        const int   c   = gtc[gbase + bestj];
        const float mx  = fmaxf(l0, fmaxf(l1, l2));
        const float lse = mx + __logf(__expf(l0 - mx) + __expf(l1 - mx) + __expf(l2 - mx));
        const float lc  = (c == 0) ? l0 : ((c == 1) ? l1 : l2);
        lsum += lse - lc;
    }

    // ---- block reduction -> per-block partial ----
    #pragma unroll
    for (int o = 16; o > 0; o >>= 1)
        lsum += __shfl_down_sync(0xFFFFFFFFu, lsum, o);

    __shared__ float ssum[TPB / 32];
    const int lane = threadIdx.x & 31;
    const int wid  = threadIdx.x >> 5;
    if (lane == 0) ssum[wid] = lsum;
    __syncthreads();
    if (threadIdx.x < TPB / 32) {
        float v = ssum[threadIdx.x];
        #pragma unroll
        for (int o = (TPB / 64); o > 0; o >>= 1)
            v += __shfl_down_sync(0xFFu, v, o);
        if (threadIdx.x == 0) g_partial[blockIdx.x] = v;
    }
}

__global__ void __launch_bounds__(1024) finalize_kernel(float* __restrict__ out) {
    double s = 0.0;
    for (int i = threadIdx.x; i < NBLK; i += 1024)
        s += (double)g_partial[i];

    #pragma unroll
    for (int o = 16; o > 0; o >>= 1)
        s += __shfl_down_sync(0xFFFFFFFFu, s, o);

    __shared__ double sd[32];
    const int lane = threadIdx.x & 31;
    const int wid  = threadIdx.x >> 5;
    if (lane == 0) sd[wid] = s;
    __syncthreads();
    if (threadIdx.x < 32) {
        double v = sd[threadIdx.x];
        #pragma unroll
        for (int o = 16; o > 0; o >>= 1)
            v += __shfl_down_sync(0xFFFFFFFFu, v, o);
        if (threadIdx.x == 0)
            out[0] = (float)(v / (double)BATCH);
    }
}

extern "C" void kernel_launch(void* const* d_in, const int* in_sizes, int n_in,
                              void* d_out, int out_size) {
    const float4* pred4 = (const float4*)d_in[0];
    const float4* gtb4  = (const float4*)d_in[1];
    const int*    gtc   = (const int*)d_in[2];
    float* out = (float*)d_out;

    yolo_loss_kernel<<<NBLK, TPB>>>(pred4, gtb4, gtc);
    finalize_kernel<<<1, 1024>>>(out);
}